// round 4
// baseline (speedup 1.0000x reference)
#include <cuda_runtime.h>
#include <math_constants.h>

#define B_      4
#define N_      16384
#define STRIDE_ 4
#define K_      20
#define D_      64
#define DK_     67
#define KFS_    68
#define M_      4096
#define NQ_     (B_*M_)     // 16384
#define HID_    128
#define OUT_    128
#define TK_     128         // keys per tile
#define QW_     8           // queries per warp
#define QB_     64          // queries per block

// scratch (no cudaMalloc allowed)
__device__ float g_kf[(size_t)B_*N_*KFS_];   // transformed features (padded rows, pad=0)
__device__ float g_kn[B_*N_];                // key squared norms
__device__ int   g_nbr[NQ_*K_];              // global neighbor indices

// ---------------------------------------------------------------------------
// Kernel 1: per-point transform -> kf, norms, and passthrough outputs
// ---------------------------------------------------------------------------
__global__ void __launch_bounds__(256) k_prep(const float* __restrict__ x,
                                              const float* __restrict__ pos,
                                              const float* __restrict__ lfr,
                                              float* __restrict__ outp,
                                              int out_size)
{
    int n = blockIdx.x * blockDim.x + threadIdx.x;
    if (n >= B_*N_) return;
    const float* xr = x + (size_t)n * D_;
    const float* R  = lfr + (size_t)n * 9;
    float r[9];
#pragma unroll
    for (int i = 0; i < 9; i++) r[i] = R[i];

    float kf[DK_];
#pragma unroll
    for (int i = 0; i < 16; i++) kf[i] = xr[i];
    // kf vectors: v'_a = sum_b lf[b,a] * v_b   (R = lframes^T)
#pragma unroll
    for (int v = 0; v < 16; v++) {
        float b0 = xr[16+3*v+0], b1 = xr[16+3*v+1], b2 = xr[16+3*v+2];
#pragma unroll
        for (int a = 0; a < 3; a++)
            kf[16+3*v+a] = r[0*3+a]*b0 + r[1*3+a]*b1 + r[2*3+a]*b2;
    }
    float p0 = pos[n*3+0], p1 = pos[n*3+1], p2 = pos[n*3+2];
    kf[64] = p0; kf[65] = p1; kf[66] = p2;

    float s = 0.f;
#pragma unroll
    for (int i = 0; i < DK_; i++) { g_kf[(size_t)n*KFS_ + i] = kf[i]; s += kf[i]*kf[i]; }
    g_kf[(size_t)n*KFS_ + 67] = 0.f;
    g_kn[n] = s;

    // passthrough outputs for query points (n % STRIDE == 0)
    if ((n & 3) == 0) {
        int b   = n >> 14;                       // n / 16384
        int qid = b*M_ + ((n & (N_-1)) >> 2);
        const int off_pos = NQ_*OUT_;            // 2097152
        const int off_bat = off_pos + NQ_*3;     // 2146304
        const int off_lf  = off_bat + NQ_;       // 2162688
        if (out_size >= off_lf + NQ_*9) {
            float* pos_out = outp + off_pos;
            float* bat_out = outp + off_bat;
            float* lf_out  = outp + off_lf;
            pos_out[qid*3+0] = p0; pos_out[qid*3+1] = p1; pos_out[qid*3+2] = p2;
            bat_out[qid] = (float)b;
#pragma unroll
            for (int i = 0; i < 9; i++) lf_out[qid*9+i] = r[i];
        }
    }
}

// ---------------------------------------------------------------------------
// Warp-distributed top-K insert: lanes 0..19 hold the kept (dist,idx);
// th = current max of kept (uniform). All lanes call this (ballot inside).
// ---------------------------------------------------------------------------
__device__ __forceinline__ void topk_insert(float d2, int gidx,
                                            float& kd, int& ki, float& th, int lane)
{
    unsigned m = __ballot_sync(0xffffffffu, d2 < th);
    while (m) {
        int src = __ffs(m) - 1; m &= m - 1;
        float v  = __shfl_sync(0xffffffffu, d2,  src);
        int   vi = __shfl_sync(0xffffffffu, gidx, src);
        if (v < th) {
            float mx = kd; int ml = lane;
#pragma unroll
            for (int off = 16; off; off >>= 1) {
                float om = __shfl_xor_sync(0xffffffffu, mx, off);
                int   ol = __shfl_xor_sync(0xffffffffu, ml, off);
                if (om > mx || (om == mx && ol < ml)) { mx = om; ml = ol; }
            }
            if (lane == ml) { kd = v; ki = vi; }
            float t = kd;
#pragma unroll
            for (int off = 16; off; off >>= 1)
                t = fmaxf(t, __shfl_xor_sync(0xffffffffu, t, off));
            th = t;
        }
    }
}

// ---------------------------------------------------------------------------
// Kernel 2: exact KNN, FMA-bound layout.
// Block = 256 threads = 8 warps; warp owns 8 queries; block owns 64 queries.
// Key tile [128][17 float4] in smem (row 272B, LDS.128 conflict-free);
// queries staged once [64][17 float4], read as broadcasts.
// d2' = kn - 2*dot (qn dropped; ordering invariant).
// ---------------------------------------------------------------------------
__global__ void __launch_bounds__(256, 3) k_knn()
{
    extern __shared__ float smem[];
    float4* skey4 = (float4*)smem;                 // [TK_][17]
    float*  skn   = smem + TK_*KFS_;               // [TK_]
    float4* sq4   = (float4*)(smem + TK_*KFS_ + TK_); // [QB_][17]

    const int tid = threadIdx.x, lane = tid & 31, w = tid >> 5;
    const int qbase = blockIdx.x * QB_;
    const int b = qbase >> 12;            // 64 | 4096 -> whole block same batch
    const int kb0 = b * N_;
    const float4* kf4 = (const float4*)g_kf;

    // stage this block's 64 query rows
    for (int i = tid; i < QB_*17; i += 256) {
        int qq = i / 17, g = i - qq*17;
        int pt = kb0 + ((qbase + qq) - b*M_) * STRIDE_;
        sq4[i] = kf4[(size_t)pt*17 + g];
    }

    float kd[QW_], th[QW_];
    int   ki[QW_];
#pragma unroll
    for (int q = 0; q < QW_; q++) {
        kd[q] = (lane < K_) ? CUDART_INF_F : -CUDART_INF_F;
        ki[q] = 0;
        th[q] = CUDART_INF_F;
    }
    const float4* sqw = sq4 + (w*QW_)*17;

    for (int tile = 0; tile < N_/TK_; tile++) {
        __syncthreads();
        {
            const float4* src = kf4 + (size_t)(kb0 + tile*TK_)*17;
            for (int i = tid; i < TK_*17; i += 256) skey4[i] = src[i];
            if (tid < TK_) skn[tid] = g_kn[kb0 + tile*TK_ + tid];
        }
        __syncthreads();

        float acc[QW_][4];
#pragma unroll
        for (int q = 0; q < QW_; q++) { acc[q][0]=0.f; acc[q][1]=0.f; acc[q][2]=0.f; acc[q][3]=0.f; }

#pragma unroll 1
        for (int g = 0; g < 17; g++) {
            float4 k0 = skey4[(lane     )*17 + g];
            float4 k1 = skey4[(lane + 32)*17 + g];
            float4 k2 = skey4[(lane + 64)*17 + g];
            float4 k3 = skey4[(lane + 96)*17 + g];
#pragma unroll
            for (int q = 0; q < QW_; q++) {
                float4 qv = sqw[q*17 + g];   // broadcast LDS.128
                acc[q][0] = fmaf(qv.x,k0.x, fmaf(qv.y,k0.y, fmaf(qv.z,k0.z, fmaf(qv.w,k0.w, acc[q][0]))));
                acc[q][1] = fmaf(qv.x,k1.x, fmaf(qv.y,k1.y, fmaf(qv.z,k1.z, fmaf(qv.w,k1.w, acc[q][1]))));
                acc[q][2] = fmaf(qv.x,k2.x, fmaf(qv.y,k2.y, fmaf(qv.z,k2.z, fmaf(qv.w,k2.w, acc[q][2]))));
                acc[q][3] = fmaf(qv.x,k3.x, fmaf(qv.y,k3.y, fmaf(qv.z,k3.z, fmaf(qv.w,k3.w, acc[q][3]))));
            }
        }

        const float kn0 = skn[lane], kn1 = skn[lane+32], kn2 = skn[lane+64], kn3 = skn[lane+96];
        const int gi = kb0 + tile*TK_ + lane;
#pragma unroll
        for (int q = 0; q < QW_; q++) {
            float d20 = kn0 - 2.f*acc[q][0];
            float d21 = kn1 - 2.f*acc[q][1];
            float d22 = kn2 - 2.f*acc[q][2];
            float d23 = kn3 - 2.f*acc[q][3];
            // fast path: one ballot over the per-lane min of the 4 candidates
            float mn = fminf(fminf(d20, d21), fminf(d22, d23));
            if (__ballot_sync(0xffffffffu, mn < th[q])) {
                topk_insert(d20, gi,    kd[q], ki[q], th[q], lane);
                topk_insert(d21, gi+32, kd[q], ki[q], th[q], lane);
                topk_insert(d22, gi+64, kd[q], ki[q], th[q], lane);
                topk_insert(d23, gi+96, kd[q], ki[q], th[q], lane);
            }
        }
    }

    if (lane < K_) {
#pragma unroll
        for (int q = 0; q < QW_; q++)
            g_nbr[(qbase + w*QW_ + q)*K_ + lane] = ki[q];
    }
}

// ---------------------------------------------------------------------------
// Kernel 3: edge MLP + maxpool. Block = 8 warps, warp = 1 query,
// 5 groups x 4 edges; lane owns 4 output columns (float4 weight loads from L1).
// ---------------------------------------------------------------------------
__global__ void __launch_bounds__(256) k_mlp(const float* __restrict__ x,
                                             const float* __restrict__ lfr,
                                             const float* __restrict__ W1,
                                             const float* __restrict__ b1,
                                             const float* __restrict__ W2,
                                             const float* __restrict__ b2,
                                             float* __restrict__ outp)
{
    __shared__ float sxd[8][D_];
    __shared__ float slf[8][12];
    __shared__ float srel[8][4][D_];
    __shared__ float srl[8][4][D_];
    __shared__ __align__(16) float sa1[8][4][HID_];

    const int tid = threadIdx.x, lane = tid & 31, w = tid >> 5;
    const int q  = blockIdx.x * 8 + w;
    const int b  = q >> 12;
    const int pt = b*N_ + (q - b*M_) * STRIDE_;

    for (int d = lane; d < D_; d += 32) sxd[w][d] = x[(size_t)pt*D_ + d];
    if (lane < 9) slf[w][lane] = lfr[(size_t)pt*9 + lane];
    __syncwarp();

    const int c4 = lane * 4;
    float4 base = *(const float4*)(b1 + c4);
#pragma unroll 8
    for (int d = 0; d < D_; d++) {
        float xv = sxd[w][d];
        float4 w4 = __ldg((const float4*)(W1 + d*HID_ + c4));
        base.x += xv*w4.x; base.y += xv*w4.y; base.z += xv*w4.z; base.w += xv*w4.w;
    }
    const float4 b2v = __ldg((const float4*)(b2 + c4));
    float4 mx = make_float4(-CUDART_INF_F, -CUDART_INF_F, -CUDART_INF_F, -CUDART_INF_F);

    for (int grp = 0; grp < 5; grp++) {
        __syncwarp();
        int s = 0;
        if (lane < 4) s = g_nbr[q*K_ + grp*4 + lane];
        const int ss0 = __shfl_sync(0xffffffffu, s, 0);
        const int ss1 = __shfl_sync(0xffffffffu, s, 1);
        const int ss2 = __shfl_sync(0xffffffffu, s, 2);
        const int ss3 = __shfl_sync(0xffffffffu, s, 3);
        {
            const float* xs0 = x + (size_t)ss0 * D_;
            const float* xs1 = x + (size_t)ss1 * D_;
            const float* xs2 = x + (size_t)ss2 * D_;
            const float* xs3 = x + (size_t)ss3 * D_;
#pragma unroll
            for (int d = lane; d < D_; d += 32) {
                float xd = sxd[w][d];
                srel[w][0][d] = xs0[d] - xd;
                srel[w][1][d] = xs1[d] - xd;
                srel[w][2][d] = xs2[d] - xd;
                srel[w][3][d] = xs3[d] - xd;
            }
        }
        __syncwarp();
        // rotate rel -> rel_local with R = lf_dst (v'_a = sum_b lf[a,b] v_b)
#pragma unroll
        for (int t = 0; t < 8; t++) {
            int item = lane + 32*t;
            int e = item >> 6;
            int d = item & 63;
            float v;
            if (d < 16) v = srel[w][e][d];
            else {
                int dd = d - 16;
                int a  = dd % 3;
                int vb = 16 + dd - a;
                v = slf[w][a*3+0]*srel[w][e][vb]
                  + slf[w][a*3+1]*srel[w][e][vb+1]
                  + slf[w][a*3+2]*srel[w][e][vb+2];
            }
            srl[w][e][d] = v;
        }
        __syncwarp();

        float4 ac0 = {0,0,0,0}, ac1 = {0,0,0,0}, ac2 = {0,0,0,0}, ac3 = {0,0,0,0};
#pragma unroll 4
        for (int d = 0; d < D_; d++) {
            float4 w4 = __ldg((const float4*)(W1 + (D_+d)*HID_ + c4));
            float r0 = srl[w][0][d], r1 = srl[w][1][d], r2 = srl[w][2][d], r3 = srl[w][3][d];
            ac0.x += r0*w4.x; ac0.y += r0*w4.y; ac0.z += r0*w4.z; ac0.w += r0*w4.w;
            ac1.x += r1*w4.x; ac1.y += r1*w4.y; ac1.z += r1*w4.z; ac1.w += r1*w4.w;
            ac2.x += r2*w4.x; ac2.y += r2*w4.y; ac2.z += r2*w4.z; ac2.w += r2*w4.w;
            ac3.x += r3*w4.x; ac3.y += r3*w4.y; ac3.z += r3*w4.z; ac3.w += r3*w4.w;
        }
        {
            float4 a;
            a.x = fmaxf(base.x+ac0.x,0.f); a.y = fmaxf(base.y+ac0.y,0.f);
            a.z = fmaxf(base.z+ac0.z,0.f); a.w = fmaxf(base.w+ac0.w,0.f);
            *(float4*)&sa1[w][0][c4] = a;
            a.x = fmaxf(base.x+ac1.x,0.f); a.y = fmaxf(base.y+ac1.y,0.f);
            a.z = fmaxf(base.z+ac1.z,0.f); a.w = fmaxf(base.w+ac1.w,0.f);
            *(float4*)&sa1[w][1][c4] = a;
            a.x = fmaxf(base.x+ac2.x,0.f); a.y = fmaxf(base.y+ac2.y,0.f);
            a.z = fmaxf(base.z+ac2.z,0.f); a.w = fmaxf(base.w+ac2.w,0.f);
            *(float4*)&sa1[w][2][c4] = a;
            a.x = fmaxf(base.x+ac3.x,0.f); a.y = fmaxf(base.y+ac3.y,0.f);
            a.z = fmaxf(base.z+ac3.z,0.f); a.w = fmaxf(base.w+ac3.w,0.f);
            *(float4*)&sa1[w][3][c4] = a;
        }
        __syncwarp();

        float4 m0 = b2v, m1 = b2v, m2 = b2v, m3 = b2v;
#pragma unroll 4
        for (int j = 0; j < HID_; j++) {
            float4 w4 = __ldg((const float4*)(W2 + j*HID_ + c4));
            float a0 = sa1[w][0][j], a1 = sa1[w][1][j], a2 = sa1[w][2][j], a3 = sa1[w][3][j];
            m0.x += a0*w4.x; m0.y += a0*w4.y; m0.z += a0*w4.z; m0.w += a0*w4.w;
            m1.x += a1*w4.x; m1.y += a1*w4.y; m1.z += a1*w4.z; m1.w += a1*w4.w;
            m2.x += a2*w4.x; m2.y += a2*w4.y; m2.z += a2*w4.z; m2.w += a2*w4.w;
            m3.x += a3*w4.x; m3.y += a3*w4.y; m3.z += a3*w4.z; m3.w += a3*w4.w;
        }
        mx.x = fmaxf(fmaxf(fmaxf(fmaxf(mx.x, m0.x), m1.x), m2.x), m3.x);
        mx.y = fmaxf(fmaxf(fmaxf(fmaxf(mx.y, m0.y), m1.y), m2.y), m3.y);
        mx.z = fmaxf(fmaxf(fmaxf(fmaxf(mx.z, m0.z), m1.z), m2.z), m3.z);
        mx.w = fmaxf(fmaxf(fmaxf(fmaxf(mx.w, m0.w), m1.w), m2.w), m3.w);
    }

    *(float4*)(outp + (size_t)q*OUT_ + c4) = mx;
}

// ---------------------------------------------------------------------------
extern "C" void kernel_launch(void* const* d_in, const int* in_sizes, int n_in,
                              void* d_out, int out_size)
{
    const float* x   = (const float*)d_in[0];
    const float* pos = (const float*)d_in[1];
    const float* lfr = (const float*)d_in[2];
    /* d_in[3] = batch (int32), derived instead */
    const float* W1  = (const float*)d_in[4];
    const float* b1  = (const float*)d_in[5];
    const float* W2  = (const float*)d_in[6];
    const float* b2  = (const float*)d_in[7];
    float* outp = (float*)d_out;

    const int knn_smem = (TK_*KFS_ + TK_ + QB_*KFS_) * (int)sizeof(float); // 52736 B
    cudaFuncSetAttribute(k_knn, cudaFuncAttributeMaxDynamicSharedMemorySize, knn_smem);

    k_prep<<<(B_*N_ + 255)/256, 256>>>(x, pos, lfr, outp, out_size);
    k_knn<<<NQ_/QB_, 256, knn_smem>>>();
    k_mlp<<<NQ_/8, 256>>>(x, lfr, W1, b1, W2, b2, outp);
}

// round 5
// speedup vs baseline: 1.1245x; 1.1245x over previous
#include <cuda_runtime.h>
#include <math_constants.h>
#include <stdint.h>

#define B_      4
#define N_      16384
#define STRIDE_ 4
#define K_      20
#define K2_     32          // tf32 candidate count
#define D_      64
#define DK_     67
#define KFS_    68
#define M_      4096
#define NQ_     (B_*M_)     // 16384
#define HID_    128
#define OUT_    128
#define TKK_    128         // keys per tile
#define QBK_    64          // queries per block (knn)
#define DROW_   132         // d2 smem row stride (16B-aligned rows)

// scratch (no cudaMalloc allowed)
__device__ float g_kf[(size_t)B_*N_*KFS_];   // transformed features fp32 (pad=0)
__device__ float g_kn[B_*N_];                // key squared norms
__device__ int   g_cand[NQ_*K2_];            // tf32 candidates
__device__ int   g_nbr[NQ_*K_];              // exact neighbor indices

__device__ __forceinline__ uint32_t to_tf32(float f) {
    uint32_t r; asm("cvt.rna.tf32.f32 %0,%1;" : "=r"(r) : "f"(f)); return r;
}
__device__ __forceinline__ void mma_tf32(float* c, uint32_t a0, uint32_t a1, uint32_t b0) {
    asm volatile("mma.sync.aligned.m16n8k4.row.col.f32.tf32.tf32.f32 "
                 "{%0,%1,%2,%3},{%4,%5},{%6},{%0,%1,%2,%3};"
                 : "+f"(c[0]), "+f"(c[1]), "+f"(c[2]), "+f"(c[3])
                 : "r"(a0), "r"(a1), "r"(b0));
}

// ---------------------------------------------------------------------------
// Kernel 1: per-point transform -> kf, norms, and passthrough outputs
// ---------------------------------------------------------------------------
__global__ void __launch_bounds__(256) k_prep(const float* __restrict__ x,
                                              const float* __restrict__ pos,
                                              const float* __restrict__ lfr,
                                              float* __restrict__ outp,
                                              int out_size)
{
    int n = blockIdx.x * blockDim.x + threadIdx.x;
    if (n >= B_*N_) return;
    const float* xr = x + (size_t)n * D_;
    const float* R  = lfr + (size_t)n * 9;
    float r[9];
#pragma unroll
    for (int i = 0; i < 9; i++) r[i] = R[i];

    float kf[DK_];
#pragma unroll
    for (int i = 0; i < 16; i++) kf[i] = xr[i];
#pragma unroll
    for (int v = 0; v < 16; v++) {
        float b0 = xr[16+3*v+0], b1 = xr[16+3*v+1], b2 = xr[16+3*v+2];
#pragma unroll
        for (int a = 0; a < 3; a++)
            kf[16+3*v+a] = r[0*3+a]*b0 + r[1*3+a]*b1 + r[2*3+a]*b2;
    }
    float p0 = pos[n*3+0], p1 = pos[n*3+1], p2 = pos[n*3+2];
    kf[64] = p0; kf[65] = p1; kf[66] = p2;

    float s = 0.f;
#pragma unroll
    for (int i = 0; i < DK_; i++) { g_kf[(size_t)n*KFS_ + i] = kf[i]; s += kf[i]*kf[i]; }
    g_kf[(size_t)n*KFS_ + 67] = 0.f;
    g_kn[n] = s;

    if ((n & 3) == 0) {
        int b   = n >> 14;
        int qid = b*M_ + ((n & (N_-1)) >> 2);
        const int off_pos = NQ_*OUT_;
        const int off_bat = off_pos + NQ_*3;
        const int off_lf  = off_bat + NQ_;
        if (out_size >= off_lf + NQ_*9) {
            float* pos_out = outp + off_pos;
            float* bat_out = outp + off_bat;
            float* lf_out  = outp + off_lf;
            pos_out[qid*3+0] = p0; pos_out[qid*3+1] = p1; pos_out[qid*3+2] = p2;
            bat_out[qid] = (float)b;
#pragma unroll
            for (int i = 0; i < 9; i++) lf_out[qid*9+i] = r[i];
        }
    }
}

// ---------------------------------------------------------------------------
// Warp-distributed top-K insert (all 32 lanes hold kept entries for K2=32)
// ---------------------------------------------------------------------------
__device__ __forceinline__ void topk_insert(float d2, int gidx,
                                            float& kd, int& ki, float& th, int lane)
{
    unsigned m = __ballot_sync(0xffffffffu, d2 < th);
    while (m) {
        int src = __ffs(m) - 1; m &= m - 1;
        float v  = __shfl_sync(0xffffffffu, d2,  src);
        int   vi = __shfl_sync(0xffffffffu, gidx, src);
        if (v < th) {
            float mx = kd; int ml = lane;
#pragma unroll
            for (int off = 16; off; off >>= 1) {
                float om = __shfl_xor_sync(0xffffffffu, mx, off);
                int   ol = __shfl_xor_sync(0xffffffffu, ml, off);
                if (om > mx || (om == mx && ol < ml)) { mx = om; ml = ol; }
            }
            if (lane == ml) { kd = v; ki = vi; }
            float t = kd;
#pragma unroll
            for (int off = 16; off; off >>= 1)
                t = fmaxf(t, __shfl_xor_sync(0xffffffffu, t, off));
            th = t;
        }
    }
}

// ---------------------------------------------------------------------------
// Kernel 2: tf32 tensor-core distance pass -> top-32 candidates per query.
// Block = 256 thr = 8 warps, 64 queries. Warp = m-tile(16q) x key-half(64k).
// Per key tile: mma -> dot tile in smem -> warp-topk scan (8 q/warp).
// ---------------------------------------------------------------------------
__global__ void __launch_bounds__(256) k_knn_tc()
{
    extern __shared__ uint32_t sh[];
    uint32_t* skq = sh;                          // [QBK_][68] tf32 queries
    uint32_t* skt = sh + QBK_*KFS_;              // [TKK_][68] tf32 keys
    float*    skn = (float*)(sh + QBK_*KFS_ + TKK_*KFS_);         // [TKK_]
    float*    sd2 = (float*)(sh + QBK_*KFS_ + TKK_*KFS_ + TKK_);  // [QBK_][DROW_]

    const int tid = threadIdx.x, lane = tid & 31, w = tid >> 5;
    const int qbase = blockIdx.x * QBK_;
    const int b = qbase >> 12;                   // 64 | 4096 => one batch/block
    const int kb0 = b * N_;

    // stage 64 query rows (tf32)
    for (int i = tid; i < QBK_*KFS_; i += 256) {
        int qq = i / KFS_, d = i - qq*KFS_;
        int pt = kb0 + ((qbase + qq) - b*M_) * STRIDE_;
        skq[i] = to_tf32(g_kf[(size_t)pt*KFS_ + d]);
    }

    float kd[8], th[8];
    int   ki[8];
#pragma unroll
    for (int j = 0; j < 8; j++) { kd[j] = CUDART_INF_F; ki[j] = 0; th[j] = CUDART_INF_F; }

    // fragment addressing
    const int mrow0 = (w >> 1)*16 + (lane >> 2);           // block-local query row
    const int kbase = (w & 1)*64;                          // key half
    const uint32_t* qA0 = skq + mrow0*KFS_ + (lane & 3);
    const uint32_t* qA1 = qA0 + 8*KFS_;
    const int col0 = kbase + 2*(lane & 3);

    for (int tile = 0; tile < N_/TKK_; tile++) {
        __syncthreads();
        {
            const float* src = g_kf + (size_t)(kb0 + tile*TKK_)*KFS_;
            for (int i = tid; i < TKK_*KFS_; i += 256) skt[i] = to_tf32(src[i]);
            if (tid < TKK_) skn[tid] = g_kn[kb0 + tile*TKK_ + tid];
        }
        __syncthreads();

        // ---- mma: dot(Q[16], K[64]) per warp, 8 n-tiles x 17 k-steps ----
        float acc[8][4];
#pragma unroll
        for (int nt = 0; nt < 8; nt++) { acc[nt][0]=0.f; acc[nt][1]=0.f; acc[nt][2]=0.f; acc[nt][3]=0.f; }
        const uint32_t* kB = skt + (kbase + (lane >> 2))*KFS_ + (lane & 3);
#pragma unroll 1
        for (int ks = 0; ks < 17; ks++) {
            uint32_t a0 = qA0[ks*4];
            uint32_t a1 = qA1[ks*4];
#pragma unroll
            for (int nt = 0; nt < 8; nt++) {
                uint32_t b0 = kB[nt*8*KFS_ + ks*4];
                mma_tf32(acc[nt], a0, a1, b0);
            }
        }
        // write dot tile
#pragma unroll
        for (int nt = 0; nt < 8; nt++) {
            *(float2*)&sd2[ mrow0     *DROW_ + col0 + nt*8] = make_float2(acc[nt][0], acc[nt][1]);
            *(float2*)&sd2[(mrow0 + 8)*DROW_ + col0 + nt*8] = make_float2(acc[nt][2], acc[nt][3]);
        }
        __syncthreads();

        // ---- scan: warp w handles block-local queries [8w, 8w+8) ----
        const float4 kn4 = ((const float4*)skn)[lane];
        const int gi0 = kb0 + tile*TKK_ + 4*lane;
#pragma unroll
        for (int j = 0; j < 8; j++) {
            const int row = w*8 + j;
            float4 dd = *(const float4*)&sd2[row*DROW_ + 4*lane];
            float d20 = kn4.x - 2.f*dd.x;
            float d21 = kn4.y - 2.f*dd.y;
            float d22 = kn4.z - 2.f*dd.z;
            float d23 = kn4.w - 2.f*dd.w;
            float mn = fminf(fminf(d20, d21), fminf(d22, d23));
            if (__ballot_sync(0xffffffffu, mn < th[j])) {
                topk_insert(d20, gi0,   kd[j], ki[j], th[j], lane);
                topk_insert(d21, gi0+1, kd[j], ki[j], th[j], lane);
                topk_insert(d22, gi0+2, kd[j], ki[j], th[j], lane);
                topk_insert(d23, gi0+3, kd[j], ki[j], th[j], lane);
            }
        }
    }

#pragma unroll
    for (int j = 0; j < 8; j++)
        g_cand[(qbase + w*8 + j)*K2_ + lane] = ki[j];
}

// ---------------------------------------------------------------------------
// Kernel 2b: exact fp32 re-rank of 32 candidates -> top-20 set.
// Warp = query, lane = candidate.
// ---------------------------------------------------------------------------
__global__ void __launch_bounds__(256) k_rerank()
{
    const int tid = threadIdx.x, lane = tid & 31, w = tid >> 5;
    const int q = blockIdx.x * 8 + w;
    const int b = q >> 12;
    const int pt = b*N_ + (q - b*M_) * STRIDE_;

    const int cand = g_cand[q*K2_ + lane];
    const float4* qr = (const float4*)(g_kf + (size_t)pt*KFS_);
    const float4* kr = (const float4*)(g_kf + (size_t)cand*KFS_);
    float dot = 0.f;
#pragma unroll
    for (int g = 0; g < 17; g++) {
        float4 a = qr[g], c = kr[g];
        dot = fmaf(a.x,c.x, fmaf(a.y,c.y, fmaf(a.z,c.z, fmaf(a.w,c.w, dot))));
    }
    float d2 = g_kn[cand] - 2.f*dot;

#pragma unroll
    for (int r = 0; r < K_; r++) {
        float mv = d2; int ml = lane;
#pragma unroll
        for (int off = 16; off; off >>= 1) {
            float om = __shfl_xor_sync(0xffffffffu, mv, off);
            int   ol = __shfl_xor_sync(0xffffffffu, ml, off);
            if (om < mv || (om == mv && ol < ml)) { mv = om; ml = ol; }
        }
        if (lane == ml) { g_nbr[q*K_ + r] = cand; d2 = CUDART_INF_F; }
    }
}

// ---------------------------------------------------------------------------
// Kernel 3: edge MLP + maxpool (unchanged R2 design).
// ---------------------------------------------------------------------------
__global__ void __launch_bounds__(256) k_mlp(const float* __restrict__ x,
                                             const float* __restrict__ lfr,
                                             const float* __restrict__ W1,
                                             const float* __restrict__ b1,
                                             const float* __restrict__ W2,
                                             const float* __restrict__ b2,
                                             float* __restrict__ outp)
{
    __shared__ float sxd[8][D_];
    __shared__ float slf[8][12];
    __shared__ float srel[8][4][D_];
    __shared__ float srl[8][4][D_];
    __shared__ __align__(16) float sa1[8][4][HID_];

    const int tid = threadIdx.x, lane = tid & 31, w = tid >> 5;
    const int q  = blockIdx.x * 8 + w;
    const int b  = q >> 12;
    const int pt = b*N_ + (q - b*M_) * STRIDE_;

    for (int d = lane; d < D_; d += 32) sxd[w][d] = x[(size_t)pt*D_ + d];
    if (lane < 9) slf[w][lane] = lfr[(size_t)pt*9 + lane];
    __syncwarp();

    const int c4 = lane * 4;
    float4 base = *(const float4*)(b1 + c4);
#pragma unroll 8
    for (int d = 0; d < D_; d++) {
        float xv = sxd[w][d];
        float4 w4 = __ldg((const float4*)(W1 + d*HID_ + c4));
        base.x += xv*w4.x; base.y += xv*w4.y; base.z += xv*w4.z; base.w += xv*w4.w;
    }
    const float4 b2v = __ldg((const float4*)(b2 + c4));
    float4 mx = make_float4(-CUDART_INF_F, -CUDART_INF_F, -CUDART_INF_F, -CUDART_INF_F);

    for (int grp = 0; grp < 5; grp++) {
        __syncwarp();
        int s = 0;
        if (lane < 4) s = g_nbr[q*K_ + grp*4 + lane];
        const int ss0 = __shfl_sync(0xffffffffu, s, 0);
        const int ss1 = __shfl_sync(0xffffffffu, s, 1);
        const int ss2 = __shfl_sync(0xffffffffu, s, 2);
        const int ss3 = __shfl_sync(0xffffffffu, s, 3);
        {
            const float* xs0 = x + (size_t)ss0 * D_;
            const float* xs1 = x + (size_t)ss1 * D_;
            const float* xs2 = x + (size_t)ss2 * D_;
            const float* xs3 = x + (size_t)ss3 * D_;
#pragma unroll
            for (int d = lane; d < D_; d += 32) {
                float xd = sxd[w][d];
                srel[w][0][d] = xs0[d] - xd;
                srel[w][1][d] = xs1[d] - xd;
                srel[w][2][d] = xs2[d] - xd;
                srel[w][3][d] = xs3[d] - xd;
            }
        }
        __syncwarp();
#pragma unroll
        for (int t = 0; t < 8; t++) {
            int item = lane + 32*t;
            int e = item >> 6;
            int d = item & 63;
            float v;
            if (d < 16) v = srel[w][e][d];
            else {
                int dd = d - 16;
                int a  = dd % 3;
                int vb = 16 + dd - a;
                v = slf[w][a*3+0]*srel[w][e][vb]
                  + slf[w][a*3+1]*srel[w][e][vb+1]
                  + slf[w][a*3+2]*srel[w][e][vb+2];
            }
            srl[w][e][d] = v;
        }
        __syncwarp();

        float4 ac0 = {0,0,0,0}, ac1 = {0,0,0,0}, ac2 = {0,0,0,0}, ac3 = {0,0,0,0};
#pragma unroll 4
        for (int d = 0; d < D_; d++) {
            float4 w4 = __ldg((const float4*)(W1 + (D_+d)*HID_ + c4));
            float r0 = srl[w][0][d], r1 = srl[w][1][d], r2 = srl[w][2][d], r3 = srl[w][3][d];
            ac0.x += r0*w4.x; ac0.y += r0*w4.y; ac0.z += r0*w4.z; ac0.w += r0*w4.w;
            ac1.x += r1*w4.x; ac1.y += r1*w4.y; ac1.z += r1*w4.z; ac1.w += r1*w4.w;
            ac2.x += r2*w4.x; ac2.y += r2*w4.y; ac2.z += r2*w4.z; ac2.w += r2*w4.w;
            ac3.x += r3*w4.x; ac3.y += r3*w4.y; ac3.z += r3*w4.z; ac3.w += r3*w4.w;
        }
        {
            float4 a;
            a.x = fmaxf(base.x+ac0.x,0.f); a.y = fmaxf(base.y+ac0.y,0.f);
            a.z = fmaxf(base.z+ac0.z,0.f); a.w = fmaxf(base.w+ac0.w,0.f);
            *(float4*)&sa1[w][0][c4] = a;
            a.x = fmaxf(base.x+ac1.x,0.f); a.y = fmaxf(base.y+ac1.y,0.f);
            a.z = fmaxf(base.z+ac1.z,0.f); a.w = fmaxf(base.w+ac1.w,0.f);
            *(float4*)&sa1[w][1][c4] = a;
            a.x = fmaxf(base.x+ac2.x,0.f); a.y = fmaxf(base.y+ac2.y,0.f);
            a.z = fmaxf(base.z+ac2.z,0.f); a.w = fmaxf(base.w+ac2.w,0.f);
            *(float4*)&sa1[w][2][c4] = a;
            a.x = fmaxf(base.x+ac3.x,0.f); a.y = fmaxf(base.y+ac3.y,0.f);
            a.z = fmaxf(base.z+ac3.z,0.f); a.w = fmaxf(base.w+ac3.w,0.f);
            *(float4*)&sa1[w][3][c4] = a;
        }
        __syncwarp();

        float4 m0 = b2v, m1 = b2v, m2 = b2v, m3 = b2v;
#pragma unroll 4
        for (int j = 0; j < HID_; j++) {
            float4 w4 = __ldg((const float4*)(W2 + j*HID_ + c4));
            float a0 = sa1[w][0][j], a1 = sa1[w][1][j], a2 = sa1[w][2][j], a3 = sa1[w][3][j];
            m0.x += a0*w4.x; m0.y += a0*w4.y; m0.z += a0*w4.z; m0.w += a0*w4.w;
            m1.x += a1*w4.x; m1.y += a1*w4.y; m1.z += a1*w4.z; m1.w += a1*w4.w;
            m2.x += a2*w4.x; m2.y += a2*w4.y; m2.z += a2*w4.z; m2.w += a2*w4.w;
            m3.x += a3*w4.x; m3.y += a3*w4.y; m3.z += a3*w4.z; m3.w += a3*w4.w;
        }
        mx.x = fmaxf(fmaxf(fmaxf(fmaxf(mx.x, m0.x), m1.x), m2.x), m3.x);
        mx.y = fmaxf(fmaxf(fmaxf(fmaxf(mx.y, m0.y), m1.y), m2.y), m3.y);
        mx.z = fmaxf(fmaxf(fmaxf(fmaxf(mx.z, m0.z), m1.z), m2.z), m3.z);
        mx.w = fmaxf(fmaxf(fmaxf(fmaxf(mx.w, m0.w), m1.w), m2.w), m3.w);
    }

    *(float4*)(outp + (size_t)q*OUT_ + c4) = mx;
}

// ---------------------------------------------------------------------------
extern "C" void kernel_launch(void* const* d_in, const int* in_sizes, int n_in,
                              void* d_out, int out_size)
{
    const float* x   = (const float*)d_in[0];
    const float* pos = (const float*)d_in[1];
    const float* lfr = (const float*)d_in[2];
    const float* W1  = (const float*)d_in[4];
    const float* b1  = (const float*)d_in[5];
    const float* W2  = (const float*)d_in[6];
    const float* b2  = (const float*)d_in[7];
    float* outp = (float*)d_out;

    const int knn_smem = (QBK_*KFS_ + TKK_*KFS_ + TKK_ + QBK_*DROW_) * 4; // 86528 B
    cudaFuncSetAttribute(k_knn_tc, cudaFuncAttributeMaxDynamicSharedMemorySize, knn_smem);

    k_prep<<<(B_*N_ + 255)/256, 256>>>(x, pos, lfr, outp, out_size);
    k_knn_tc<<<NQ_/QBK_, 256, knn_smem>>>();
    k_rerank<<<NQ_/8, 256>>>();
    k_mlp<<<NQ_/8, 256>>>(x, lfr, W1, b1, W2, b2, outp);
}

// round 6
// speedup vs baseline: 1.1327x; 1.0072x over previous
#include <cuda_runtime.h>
#include <math_constants.h>
#include <stdint.h>

#define B_      4
#define N_      16384
#define STRIDE_ 4
#define K_      20
#define K2_     32          // tf32 candidate count
#define D_      64
#define DK_     67
#define KFS_    68
#define M_      4096
#define NQ_     (B_*M_)     // 16384
#define HID_    128
#define OUT_    128
#define TKK_    128         // keys per tile
#define QBK_    64          // queries per block (knn)
#define DROW_   132         // d2 smem row stride
#define SUB_    20          // permuted sub-row stride (words, 16B aligned)
#define KP_     80          // permuted row stride (words)

// scratch (no cudaMalloc allowed)
__device__ float g_kf[(size_t)B_*N_*KFS_];   // transformed features fp32 (pad=0)
__device__ float g_kn[B_*N_];                // key squared norms
__device__ int   g_cand[NQ_*K2_];            // tf32 candidates
__device__ int   g_nbr[NQ_*K_];              // exact neighbor indices

__device__ __forceinline__ uint32_t to_tf32(float f) {
    uint32_t r; asm("cvt.rna.tf32.f32 %0,%1;" : "=r"(r) : "f"(f)); return r;
}
__device__ __forceinline__ void mma_tf32_k8(float* c,
    uint32_t a0, uint32_t a1, uint32_t a2, uint32_t a3, uint32_t b0, uint32_t b1) {
    asm volatile("mma.sync.aligned.m16n8k8.row.col.f32.tf32.tf32.f32 "
                 "{%0,%1,%2,%3},{%4,%5,%6,%7},{%8,%9},{%0,%1,%2,%3};"
                 : "+f"(c[0]), "+f"(c[1]), "+f"(c[2]), "+f"(c[3])
                 : "r"(a0), "r"(a1), "r"(a2), "r"(a3), "r"(b0), "r"(b1));
}

// ---------------------------------------------------------------------------
// Kernel 1: per-point transform -> kf, norms, and passthrough outputs
// ---------------------------------------------------------------------------
__global__ void __launch_bounds__(256) k_prep(const float* __restrict__ x,
                                              const float* __restrict__ pos,
                                              const float* __restrict__ lfr,
                                              float* __restrict__ outp,
                                              int out_size)
{
    int n = blockIdx.x * blockDim.x + threadIdx.x;
    if (n >= B_*N_) return;
    const float* xr = x + (size_t)n * D_;
    const float* R  = lfr + (size_t)n * 9;
    float r[9];
#pragma unroll
    for (int i = 0; i < 9; i++) r[i] = R[i];

    float kf[DK_];
#pragma unroll
    for (int i = 0; i < 16; i++) kf[i] = xr[i];
#pragma unroll
    for (int v = 0; v < 16; v++) {
        float b0 = xr[16+3*v+0], b1 = xr[16+3*v+1], b2 = xr[16+3*v+2];
#pragma unroll
        for (int a = 0; a < 3; a++)
            kf[16+3*v+a] = r[0*3+a]*b0 + r[1*3+a]*b1 + r[2*3+a]*b2;
    }
    float p0 = pos[n*3+0], p1 = pos[n*3+1], p2 = pos[n*3+2];
    kf[64] = p0; kf[65] = p1; kf[66] = p2;

    float s = 0.f;
#pragma unroll
    for (int i = 0; i < DK_; i++) { g_kf[(size_t)n*KFS_ + i] = kf[i]; s += kf[i]*kf[i]; }
    g_kf[(size_t)n*KFS_ + 67] = 0.f;
    g_kn[n] = s;

    if ((n & 3) == 0) {
        int b   = n >> 14;
        int qid = b*M_ + ((n & (N_-1)) >> 2);
        const int off_pos = NQ_*OUT_;
        const int off_bat = off_pos + NQ_*3;
        const int off_lf  = off_bat + NQ_;
        if (out_size >= off_lf + NQ_*9) {
            float* pos_out = outp + off_pos;
            float* bat_out = outp + off_bat;
            float* lf_out  = outp + off_lf;
            pos_out[qid*3+0] = p0; pos_out[qid*3+1] = p1; pos_out[qid*3+2] = p2;
            bat_out[qid] = (float)b;
#pragma unroll
            for (int i = 0; i < 9; i++) lf_out[qid*9+i] = r[i];
        }
    }
}

// ---------------------------------------------------------------------------
// Warp-distributed top-K insert (32 kept entries for K2=32)
// ---------------------------------------------------------------------------
__device__ __forceinline__ void topk_insert(float d2, int gidx,
                                            float& kd, int& ki, float& th, int lane)
{
    unsigned m = __ballot_sync(0xffffffffu, d2 < th);
    while (m) {
        int src = __ffs(m) - 1; m &= m - 1;
        float v  = __shfl_sync(0xffffffffu, d2,  src);
        int   vi = __shfl_sync(0xffffffffu, gidx, src);
        if (v < th) {
            float mx = kd; int ml = lane;
#pragma unroll
            for (int off = 16; off; off >>= 1) {
                float om = __shfl_xor_sync(0xffffffffu, mx, off);
                int   ol = __shfl_xor_sync(0xffffffffu, ml, off);
                if (om > mx || (om == mx && ol < ml)) { mx = om; ml = ol; }
            }
            if (lane == ml) { kd = v; ki = vi; }
            float t = kd;
#pragma unroll
            for (int off = 16; off; off >>= 1)
                t = fmaxf(t, __shfl_xor_sync(0xffffffffu, t, off));
            th = t;
        }
    }
}

// ---------------------------------------------------------------------------
// Kernel 2: tf32 m16n8k8 distance pass -> top-32 candidates per query.
// Permuted smem layout: element d of a row at slot (d&3)*SUB_ + (d>>2),
// so each thread's full k-fragment sequence = 20 contiguous words (5 LDS.128).
// ---------------------------------------------------------------------------
__global__ void __launch_bounds__(256, 2) k_knn_tc()
{
    extern __shared__ uint32_t sh[];
    uint32_t* skq = sh;                               // [QBK_][KP_]
    uint32_t* skt = sh + QBK_*KP_;                    // [TKK_][KP_]
    float*    skn = (float*)(sh + QBK_*KP_ + TKK_*KP_);           // [TKK_]
    float*    sd2 = (float*)(sh + QBK_*KP_ + TKK_*KP_ + TKK_);    // [QBK_][DROW_]

    const int tid = threadIdx.x, lane = tid & 31, w = tid >> 5;
    const int qbase = blockIdx.x * QBK_;
    const int b = qbase >> 12;
    const int kb0 = b * N_;

    // zero the pad slots (g = 17..19 of every sub-row), written once
    for (int i = tid; i < (QBK_ + TKK_)*4*3; i += 256) {
        int r = i / 12, jj = (i % 12) / 3, g = 17 + (i % 3);
        uint32_t* base = (r < QBK_) ? (skq + r*KP_) : (skt + (r - QBK_)*KP_);
        base[jj*SUB_ + g] = 0;
    }

    // stage 64 query rows (tf32, permuted)
    for (int i = tid; i < QBK_*17; i += 256) {
        int qq = i / 17, g = i - qq*17;
        int pt = kb0 + ((qbase + qq) - b*M_) * STRIDE_;
        float4 v = ((const float4*)(g_kf + (size_t)pt*KFS_))[g];
        uint32_t* row = skq + qq*KP_ + g;
        row[0*SUB_] = to_tf32(v.x);
        row[1*SUB_] = to_tf32(v.y);
        row[2*SUB_] = to_tf32(v.z);
        row[3*SUB_] = to_tf32(v.w);
    }

    float kd[8], th[8];
    int   ki[8];
#pragma unroll
    for (int j = 0; j < 8; j++) { kd[j] = CUDART_INF_F; ki[j] = 0; th[j] = CUDART_INF_F; }

    const int mrow0 = (w >> 1)*16 + (lane >> 2);   // block-local query row
    const int kbase = (w & 1)*64;                  // key half
    const int kk    = lane & 3;
    const int col0  = kbase + 2*kk;

    for (int tile = 0; tile < N_/TKK_; tile++) {
        __syncthreads();
        {
            const float4* src = (const float4*)(g_kf + (size_t)(kb0 + tile*TKK_)*KFS_);
            for (int i = tid; i < TKK_*17; i += 256) {
                int n = i / 17, g = i - n*17;
                float4 v = src[(size_t)n*17 + g];
                uint32_t* row = skt + n*KP_ + g;
                row[0*SUB_] = to_tf32(v.x);
                row[1*SUB_] = to_tf32(v.y);
                row[2*SUB_] = to_tf32(v.z);
                row[3*SUB_] = to_tf32(v.w);
            }
            if (tid < TKK_) skn[tid] = g_kn[kb0 + tile*TKK_ + tid];
        }
        __syncthreads();

        // ---- A fragments: 2 query rows x 20 words (constant per tile) ----
        uint4 A0v[5], A1v[5];
        {
            const uint4* p0 = (const uint4*)(skq + mrow0*KP_ + kk*SUB_);
            const uint4* p1 = (const uint4*)(skq + (mrow0+8)*KP_ + kk*SUB_);
#pragma unroll
            for (int i = 0; i < 5; i++) { A0v[i] = p0[i]; A1v[i] = p1[i]; }
        }
        const uint32_t* A0 = (const uint32_t*)A0v;
        const uint32_t* A1 = (const uint32_t*)A1v;

        float acc[8][4];
#pragma unroll
        for (int nt = 0; nt < 8; nt++) { acc[nt][0]=0.f; acc[nt][1]=0.f; acc[nt][2]=0.f; acc[nt][3]=0.f; }

#pragma unroll
        for (int nt = 0; nt < 8; nt++) {
            uint4 Bv[5];
            const uint4* bp = (const uint4*)(skt + (kbase + nt*8 + (lane >> 2))*KP_ + kk*SUB_);
#pragma unroll
            for (int i = 0; i < 5; i++) Bv[i] = bp[i];
            const uint32_t* Bf = (const uint32_t*)Bv;
#pragma unroll
            for (int ks = 0; ks < 9; ks++) {
                mma_tf32_k8(acc[nt], A0[2*ks], A1[2*ks], A0[2*ks+1], A1[2*ks+1],
                            Bf[2*ks], Bf[2*ks+1]);
            }
        }

        // write dot tile
#pragma unroll
        for (int nt = 0; nt < 8; nt++) {
            *(float2*)&sd2[ mrow0     *DROW_ + col0 + nt*8] = make_float2(acc[nt][0], acc[nt][1]);
            *(float2*)&sd2[(mrow0 + 8)*DROW_ + col0 + nt*8] = make_float2(acc[nt][2], acc[nt][3]);
        }
        __syncthreads();

        // ---- scan: warp w handles block-local queries [8w, 8w+8) ----
        const float4 kn4 = ((const float4*)skn)[lane];
        const int gi0 = kb0 + tile*TKK_ + 4*lane;
#pragma unroll
        for (int j = 0; j < 8; j++) {
            const int row = w*8 + j;
            float4 dd = *(const float4*)&sd2[row*DROW_ + 4*lane];
            float d20 = kn4.x - 2.f*dd.x;
            float d21 = kn4.y - 2.f*dd.y;
            float d22 = kn4.z - 2.f*dd.z;
            float d23 = kn4.w - 2.f*dd.w;
            float mn = fminf(fminf(d20, d21), fminf(d22, d23));
            if (__ballot_sync(0xffffffffu, mn < th[j])) {
                topk_insert(d20, gi0,   kd[j], ki[j], th[j], lane);
                topk_insert(d21, gi0+1, kd[j], ki[j], th[j], lane);
                topk_insert(d22, gi0+2, kd[j], ki[j], th[j], lane);
                topk_insert(d23, gi0+3, kd[j], ki[j], th[j], lane);
            }
        }
    }

#pragma unroll
    for (int j = 0; j < 8; j++)
        g_cand[(qbase + w*8 + j)*K2_ + lane] = ki[j];
}

// ---------------------------------------------------------------------------
// Kernel 2b: exact fp32 re-rank of 32 candidates -> top-20 set.
// ---------------------------------------------------------------------------
__global__ void __launch_bounds__(256) k_rerank()
{
    const int tid = threadIdx.x, lane = tid & 31, w = tid >> 5;
    const int q = blockIdx.x * 8 + w;
    const int b = q >> 12;
    const int pt = b*N_ + (q - b*M_) * STRIDE_;

    const int cand = g_cand[q*K2_ + lane];
    const float4* qr = (const float4*)(g_kf + (size_t)pt*KFS_);
    const float4* kr = (const float4*)(g_kf + (size_t)cand*KFS_);
    float dot = 0.f;
#pragma unroll
    for (int g = 0; g < 17; g++) {
        float4 a = qr[g], c = kr[g];
        dot = fmaf(a.x,c.x, fmaf(a.y,c.y, fmaf(a.z,c.z, fmaf(a.w,c.w, dot))));
    }
    float d2 = g_kn[cand] - 2.f*dot;

#pragma unroll
    for (int r = 0; r < K_; r++) {
        float mv = d2; int ml = lane;
#pragma unroll
        for (int off = 16; off; off >>= 1) {
            float om = __shfl_xor_sync(0xffffffffu, mv, off);
            int   ol = __shfl_xor_sync(0xffffffffu, ml, off);
            if (om < mv || (om == mv && ol < ml)) { mv = om; ml = ol; }
        }
        if (lane == ml) { g_nbr[q*K_ + r] = cand; d2 = CUDART_INF_F; }
    }
}

// ---------------------------------------------------------------------------
// Kernel 3: edge MLP + maxpool (unchanged).
// ---------------------------------------------------------------------------
__global__ void __launch_bounds__(256) k_mlp(const float* __restrict__ x,
                                             const float* __restrict__ lfr,
                                             const float* __restrict__ W1,
                                             const float* __restrict__ b1,
                                             const float* __restrict__ W2,
                                             const float* __restrict__ b2,
                                             float* __restrict__ outp)
{
    __shared__ float sxd[8][D_];
    __shared__ float slf[8][12];
    __shared__ float srel[8][4][D_];
    __shared__ float srl[8][4][D_];
    __shared__ __align__(16) float sa1[8][4][HID_];

    const int tid = threadIdx.x, lane = tid & 31, w = tid >> 5;
    const int q  = blockIdx.x * 8 + w;
    const int b  = q >> 12;
    const int pt = b*N_ + (q - b*M_) * STRIDE_;

    for (int d = lane; d < D_; d += 32) sxd[w][d] = x[(size_t)pt*D_ + d];
    if (lane < 9) slf[w][lane] = lfr[(size_t)pt*9 + lane];
    __syncwarp();

    const int c4 = lane * 4;
    float4 base = *(const float4*)(b1 + c4);
#pragma unroll 8
    for (int d = 0; d < D_; d++) {
        float xv = sxd[w][d];
        float4 w4 = __ldg((const float4*)(W1 + d*HID_ + c4));
        base.x += xv*w4.x; base.y += xv*w4.y; base.z += xv*w4.z; base.w += xv*w4.w;
    }
    const float4 b2v = __ldg((const float4*)(b2 + c4));
    float4 mx = make_float4(-CUDART_INF_F, -CUDART_INF_F, -CUDART_INF_F, -CUDART_INF_F);

    for (int grp = 0; grp < 5; grp++) {
        __syncwarp();
        int s = 0;
        if (lane < 4) s = g_nbr[q*K_ + grp*4 + lane];
        const int ss0 = __shfl_sync(0xffffffffu, s, 0);
        const int ss1 = __shfl_sync(0xffffffffu, s, 1);
        const int ss2 = __shfl_sync(0xffffffffu, s, 2);
        const int ss3 = __shfl_sync(0xffffffffu, s, 3);
        {
            const float* xs0 = x + (size_t)ss0 * D_;
            const float* xs1 = x + (size_t)ss1 * D_;
            const float* xs2 = x + (size_t)ss2 * D_;
            const float* xs3 = x + (size_t)ss3 * D_;
#pragma unroll
            for (int d = lane; d < D_; d += 32) {
                float xd = sxd[w][d];
                srel[w][0][d] = xs0[d] - xd;
                srel[w][1][d] = xs1[d] - xd;
                srel[w][2][d] = xs2[d] - xd;
                srel[w][3][d] = xs3[d] - xd;
            }
        }
        __syncwarp();
#pragma unroll
        for (int t = 0; t < 8; t++) {
            int item = lane + 32*t;
            int e = item >> 6;
            int d = item & 63;
            float v;
            if (d < 16) v = srel[w][e][d];
            else {
                int dd = d - 16;
                int a  = dd % 3;
                int vb = 16 + dd - a;
                v = slf[w][a*3+0]*srel[w][e][vb]
                  + slf[w][a*3+1]*srel[w][e][vb+1]
                  + slf[w][a*3+2]*srel[w][e][vb+2];
            }
            srl[w][e][d] = v;
        }
        __syncwarp();

        float4 ac0 = {0,0,0,0}, ac1 = {0,0,0,0}, ac2 = {0,0,0,0}, ac3 = {0,0,0,0};
#pragma unroll 4
        for (int d = 0; d < D_; d++) {
            float4 w4 = __ldg((const float4*)(W1 + (D_+d)*HID_ + c4));
            float r0 = srl[w][0][d], r1 = srl[w][1][d], r2 = srl[w][2][d], r3 = srl[w][3][d];
            ac0.x += r0*w4.x; ac0.y += r0*w4.y; ac0.z += r0*w4.z; ac0.w += r0*w4.w;
            ac1.x += r1*w4.x; ac1.y += r1*w4.y; ac1.z += r1*w4.z; ac1.w += r1*w4.w;
            ac2.x += r2*w4.x; ac2.y += r2*w4.y; ac2.z += r2*w4.z; ac2.w += r2*w4.w;
            ac3.x += r3*w4.x; ac3.y += r3*w4.y; ac3.z += r3*w4.z; ac3.w += r3*w4.w;
        }
        {
            float4 a;
            a.x = fmaxf(base.x+ac0.x,0.f); a.y = fmaxf(base.y+ac0.y,0.f);
            a.z = fmaxf(base.z+ac0.z,0.f); a.w = fmaxf(base.w+ac0.w,0.f);
            *(float4*)&sa1[w][0][c4] = a;
            a.x = fmaxf(base.x+ac1.x,0.f); a.y = fmaxf(base.y+ac1.y,0.f);
            a.z = fmaxf(base.z+ac1.z,0.f); a.w = fmaxf(base.w+ac1.w,0.f);
            *(float4*)&sa1[w][1][c4] = a;
            a.x = fmaxf(base.x+ac2.x,0.f); a.y = fmaxf(base.y+ac2.y,0.f);
            a.z = fmaxf(base.z+ac2.z,0.f); a.w = fmaxf(base.w+ac2.w,0.f);
            *(float4*)&sa1[w][2][c4] = a;
            a.x = fmaxf(base.x+ac3.x,0.f); a.y = fmaxf(base.y+ac3.y,0.f);
            a.z = fmaxf(base.z+ac3.z,0.f); a.w = fmaxf(base.w+ac3.w,0.f);
            *(float4*)&sa1[w][3][c4] = a;
        }
        __syncwarp();

        float4 m0 = b2v, m1 = b2v, m2 = b2v, m3 = b2v;
#pragma unroll 4
        for (int j = 0; j < HID_; j++) {
            float4 w4 = __ldg((const float4*)(W2 + j*HID_ + c4));
            float a0 = sa1[w][0][j], a1 = sa1[w][1][j], a2 = sa1[w][2][j], a3 = sa1[w][3][j];
            m0.x += a0*w4.x; m0.y += a0*w4.y; m0.z += a0*w4.z; m0.w += a0*w4.w;
            m1.x += a1*w4.x; m1.y += a1*w4.y; m1.z += a1*w4.z; m1.w += a1*w4.w;
            m2.x += a2*w4.x; m2.y += a2*w4.y; m2.z += a2*w4.z; m2.w += a2*w4.w;
            m3.x += a3*w4.x; m3.y += a3*w4.y; m3.z += a3*w4.z; m3.w += a3*w4.w;
        }
        mx.x = fmaxf(fmaxf(fmaxf(fmaxf(mx.x, m0.x), m1.x), m2.x), m3.x);
        mx.y = fmaxf(fmaxf(fmaxf(fmaxf(mx.y, m0.y), m1.y), m2.y), m3.y);
        mx.z = fmaxf(fmaxf(fmaxf(fmaxf(mx.z, m0.z), m1.z), m2.z), m3.z);
        mx.w = fmaxf(fmaxf(fmaxf(fmaxf(mx.w, m0.w), m1.w), m2.w), m3.w);
    }

    *(float4*)(outp + (size_t)q*OUT_ + c4) = mx;
}

// ---------------------------------------------------------------------------
extern "C" void kernel_launch(void* const* d_in, const int* in_sizes, int n_in,
                              void* d_out, int out_size)
{
    const float* x   = (const float*)d_in[0];
    const float* pos = (const float*)d_in[1];
    const float* lfr = (const float*)d_in[2];
    const float* W1  = (const float*)d_in[4];
    const float* b1  = (const float*)d_in[5];
    const float* W2  = (const float*)d_in[6];
    const float* b2  = (const float*)d_in[7];
    float* outp = (float*)d_out;

    const int knn_smem = (QBK_*KP_ + TKK_*KP_ + TKK_ + QBK_*DROW_) * 4; // 95744 B
    cudaFuncSetAttribute(k_knn_tc, cudaFuncAttributeMaxDynamicSharedMemorySize, knn_smem);

    k_prep<<<(B_*N_ + 255)/256, 256>>>(x, pos, lfr, outp, out_size);
    k_knn_tc<<<NQ_/QBK_, 256, knn_smem>>>();
    k_rerank<<<NQ_/8, 256>>>();
    k_mlp<<<NQ_/8, 256>>>(x, lfr, W1, b1, W2, b2, outp);
}